// round 2
// baseline (speedup 1.0000x reference)
#include <cuda_runtime.h>

// Problem constants
#define IN_CH   256
#define KDIM    2304      // Q*64 = C*9
#define NCH     512       // P*64 output channels
#define MPOS    8192      // B*1024 GEMM rows
#define BATCH   8

// Scratch (device globals — no runtime allocation allowed)
__device__ float g_col[(size_t)KDIM * MPOS];   // gathered activations, [j][n]
__device__ float g_wexp[(size_t)KDIM * NCH];   // expanded circulant weights, [j][ch]

// ---------------------------------------------------------------------------
// Kernel 1: expand block-circulant weights w[P=8][Q=36][64] into dense
// Wexp[j = q*64+s][ch = p*64+t] = w[p, q, (t - s) & 63]
// ---------------------------------------------------------------------------
__global__ void wexpand_kernel(const float* __restrict__ w) {
    int idx = blockIdx.x * blockDim.x + threadIdx.x;
    if (idx >= KDIM * NCH) return;
    int j = idx >> 9;          // / 512
    int n = idx & 511;
    int q = j >> 6, s = j & 63;
    int p = n >> 6, t = n & 63;
    g_wexp[idx] = w[(p * 36 + q) * 64 + ((t - s) & 63)];
}

// ---------------------------------------------------------------------------
// Kernel 2: replicate the reference's scrambled reshape.
// GEMM row n = b*1024 + m reads xu_flat[n*2304 + j]:
//   rem = m*2304 + j ;  f = rem>>10 ; l = rem&1023
//   xu[b, f, l] = unfold: f = c*9 + di*3 + dj, l = i*32 + jj,
//   value = x[b, c, i+di-1, jj+dj-1]  (zero pad outside)
// Write g_col[j][n] — coalesced along n.
// ---------------------------------------------------------------------------
__global__ void im2col_kernel(const float* __restrict__ x) {
    int n = blockIdx.x * blockDim.x + threadIdx.x;   // 0..8191
    int j = blockIdx.y;                              // 0..2303
    int b = n >> 10;
    int m = n & 1023;
    int rem = m * 2304 + j;
    int f = rem >> 10;        // 0..2303
    int l = rem & 1023;
    int c  = f / 9;
    int r  = f - c * 9;
    int di = r / 3;
    int dj = r - di * 3;
    int i  = l >> 5;
    int jj = l & 31;
    int ii = i + di - 1;
    int jc = jj + dj - 1;
    float v = 0.0f;
    if ((unsigned)ii < 32u && (unsigned)jc < 32u)
        v = x[((b * IN_CH + c) * 32 + ii) * 32 + jc];
    g_col[(size_t)j * MPOS + n] = v;
}

// ---------------------------------------------------------------------------
// Kernel 3: SGEMM  C[ch][n] = sum_j Wexp[j][ch] * col[j][n]
// BM=128 (channels), BN=128 (rows n), BK=8, 256 threads, 8x8 micro-tile.
// Epilogue writes out[b][ch][pos] directly (pos = n & 1023).
// ---------------------------------------------------------------------------
__global__ __launch_bounds__(256, 2) void gemm_kernel(float* __restrict__ out) {
    const int m0 = blockIdx.y * 128;   // channel tile origin
    const int n0 = blockIdx.x * 128;   // row tile origin

    __shared__ float As[8][128];       // [k][channel]
    __shared__ float Bs[8][128];       // [k][row]

    const int tid = threadIdx.x;
    const int tx = tid & 15;           // row micro-tile
    const int ty = tid >> 4;           // channel micro-tile

    const int lr = tid >> 5;           // 0..7  (k row within tile)
    const int lc = (tid & 31) << 2;    // 0..124 (float4 column)

    const float* Aptr = g_wexp + (size_t)lr * NCH  + m0 + lc;
    const float* Bptr = g_col  + (size_t)lr * MPOS + n0 + lc;

    float acc[8][8];
    #pragma unroll
    for (int i = 0; i < 8; i++)
        #pragma unroll
        for (int jq = 0; jq < 8; jq++) acc[i][jq] = 0.0f;

    for (int k0 = 0; k0 < KDIM; k0 += 8) {
        float4 a4 = *(const float4*)Aptr;
        float4 b4 = *(const float4*)Bptr;
        *(float4*)&As[lr][lc] = a4;
        *(float4*)&Bs[lr][lc] = b4;
        __syncthreads();

        #pragma unroll
        for (int kk = 0; kk < 8; kk++) {
            float a[8], b[8];
            *(float4*)&a[0] = *(const float4*)&As[kk][ty * 8];
            *(float4*)&a[4] = *(const float4*)&As[kk][ty * 8 + 4];
            *(float4*)&b[0] = *(const float4*)&Bs[kk][tx * 8];
            *(float4*)&b[4] = *(const float4*)&Bs[kk][tx * 8 + 4];
            #pragma unroll
            for (int i = 0; i < 8; i++)
                #pragma unroll
                for (int jq = 0; jq < 8; jq++)
                    acc[i][jq] = fmaf(a[i], b[jq], acc[i][jq]);
        }
        __syncthreads();

        Aptr += 8 * NCH;
        Bptr += 8 * MPOS;
    }

    // Epilogue: out[b, ch, pos]; a 128-row tile stays within one batch.
    const int b    = n0 >> 10;
    const int pos0 = n0 & 1023;
    float* obase = out + (size_t)b * (NCH * 1024) + pos0 + tx * 8;

    #pragma unroll
    for (int i = 0; i < 8; i++) {
        const int ch = m0 + ty * 8 + i;
        float* orow = obase + (size_t)ch * 1024;
        *(float4*)orow       = make_float4(acc[i][0], acc[i][1], acc[i][2], acc[i][3]);
        *(float4*)(orow + 4) = make_float4(acc[i][4], acc[i][5], acc[i][6], acc[i][7]);
    }
}

// ---------------------------------------------------------------------------
extern "C" void kernel_launch(void* const* d_in, const int* in_sizes, int n_in,
                              void* d_out, int out_size) {
    const float* x = (const float*)d_in[0];   // [8, 256, 32, 32]
    const float* w = (const float*)d_in[1];   // [8, 36, 64]
    float* out = (float*)d_out;               // [8, 512, 32, 32]

    wexpand_kernel<<<(KDIM * NCH + 255) / 256, 256>>>(w);
    im2col_kernel<<<dim3(MPOS / 256, KDIM), 256>>>(x);
    gemm_kernel<<<dim3(MPOS / 128, NCH / 128), 256>>>(out);
}

// round 4
// speedup vs baseline: 2.9087x; 2.9087x over previous
#include <cuda_runtime.h>
#include <cuda_bf16.h>
#include <cstdint>

#define KDIM  2304
#define K2    6912          // 3 * KDIM (split-product tripled K)
#define NCH   512
#define MPOS  8192
#define IN_CH 256

// Scratch globals (no runtime allocation allowed)
__device__ __nv_bfloat16 g_w2[(size_t)NCH  * K2];   // [ch][kk]  = [Whi | Whi | Wlo]
__device__ __nv_bfloat16 g_c2[(size_t)MPOS * K2];   // [n][kk]   = [Chi | Clo | Chi]

// ---------------- helpers ----------------
static __device__ __forceinline__ uint32_t smem_u32(const void* p) {
    uint32_t a;
    asm("{ .reg .u64 t; cvta.to.shared.u64 t, %1; cvt.u32.u64 %0, t; }" : "=r"(a) : "l"(p));
    return a;
}
static __device__ __forceinline__ void cp_async16(uint32_t dst, const void* src) {
    asm volatile("cp.async.cg.shared.global [%0], [%1], 16;" :: "r"(dst), "l"(src));
}
#define CP_COMMIT() asm volatile("cp.async.commit_group;" ::: "memory")
#define CP_WAIT(N)  asm volatile("cp.async.wait_group %0;" :: "n"(N) : "memory")

static __device__ __forceinline__ void ldsm4(uint32_t* r, uint32_t a) {
    asm volatile("ldmatrix.sync.aligned.m8n8.x4.shared.b16 {%0,%1,%2,%3}, [%4];"
        : "=r"(r[0]), "=r"(r[1]), "=r"(r[2]), "=r"(r[3]) : "r"(a));
}
static __device__ __forceinline__ void mma16816(float* d, const uint32_t* a, const uint32_t* b) {
    asm volatile(
        "mma.sync.aligned.m16n8k16.row.col.f32.bf16.bf16.f32 "
        "{%0,%1,%2,%3}, {%4,%5,%6,%7}, {%8,%9}, {%0,%1,%2,%3};"
        : "+f"(d[0]), "+f"(d[1]), "+f"(d[2]), "+f"(d[3])
        : "r"(a[0]), "r"(a[1]), "r"(a[2]), "r"(a[3]), "r"(b[0]), "r"(b[1]));
}

// ---------------------------------------------------------------------------
// Kernel 1: circulant weight expansion -> bf16 hi/lo into tripled-K layout.
// Wexp[ch = p*64+t][k = q*64+s] = w[p, q, (t-s)&63]
// ---------------------------------------------------------------------------
__global__ void wexpand_split(const float* __restrict__ w) {
    int idx = blockIdx.x * blockDim.x + threadIdx.x;    // over 512*2304
    if (idx >= NCH * KDIM) return;
    int ch = idx / KDIM;
    int k  = idx - ch * KDIM;
    int p = ch >> 6, t = ch & 63;
    int q = k >> 6,  s = k & 63;
    float v = w[(p * 36 + q) * 64 + ((t - s) & 63)];
    __nv_bfloat16 hi = __float2bfloat16(v);
    __nv_bfloat16 lo = __float2bfloat16(v - __bfloat162float(hi));
    size_t base = (size_t)ch * K2;
    g_w2[base + k]            = hi;
    g_w2[base + KDIM + k]     = hi;   // pairs with Clo
    g_w2[base + 2 * KDIM + k] = lo;   // pairs with Chi
}

// ---------------------------------------------------------------------------
// Kernel 2: scrambled-reshape gather -> bf16 hi/lo into tripled-K layout.
// row n = b*1024+m reads xu_flat[n*2304+j]:
//   rem = m*2304+j; f = rem>>10; l = rem&1023
//   f = c*9+di*3+dj, l = i*32+jj, value = x[b,c,i+di-1,jj+dj-1] (zero-pad)
// ---------------------------------------------------------------------------
__global__ void im2col_split(const float* __restrict__ x) {
    int j = (blockIdx.x * blockDim.x + threadIdx.x) * 2;   // even, 0..2302
    int n = blockIdx.y;
    int b = n >> 10;
    int m = n & 1023;
    float v[2];
    #pragma unroll
    for (int u = 0; u < 2; u++) {
        int rem = m * KDIM + j + u;
        int f = rem >> 10;
        int l = rem & 1023;
        int c  = f / 9;
        int r  = f - c * 9;
        int di = r / 3;
        int dj = r - di * 3;
        int i  = l >> 5;
        int jj = l & 31;
        int ii = i + di - 1;
        int jc = jj + dj - 1;
        float t = 0.0f;
        if ((unsigned)ii < 32u && (unsigned)jc < 32u)
            t = x[((b * IN_CH + c) * 32 + ii) * 32 + jc];
        v[u] = t;
    }
    __nv_bfloat16 h0 = __float2bfloat16(v[0]), h1 = __float2bfloat16(v[1]);
    __nv_bfloat16 l0 = __float2bfloat16(v[0] - __bfloat162float(h0));
    __nv_bfloat16 l1 = __float2bfloat16(v[1] - __bfloat162float(h1));
    size_t base = (size_t)n * K2 + j;
    *(__nv_bfloat162*)(g_c2 + base)            = __halves2bfloat162(h0, h1);
    *(__nv_bfloat162*)(g_c2 + base + KDIM)     = __halves2bfloat162(l0, l1);
    *(__nv_bfloat162*)(g_c2 + base + 2 * KDIM) = __halves2bfloat162(h0, h1);
}

// ---------------------------------------------------------------------------
// Kernel 3: bf16 mma.sync GEMM.  C[ch][n] = sum_kk W2[ch][kk] * C2[n][kk]
// BM=128, BN=128, BK=64, 3-stage cp.async pipeline, 8 warps (64x32 each).
// Smem rows = 128B (64 bf16), 3-bit xor swizzle -> conflict-free ldmatrix.
// ---------------------------------------------------------------------------
#define BK        64
#define NKITER    (K2 / BK)          // 108
#define A_BYTES   (128 * 128)        // 16 KB
#define STAGE_BYTES (2 * A_BYTES)    // A + B = 32 KB
#define STAGES    3
#define SMEM_TOTAL (STAGES * STAGE_BYTES)   // 96 KB

__global__ __launch_bounds__(256, 2) void gemm_mma(float* __restrict__ out) {
    extern __shared__ char smem[];
    const int tid  = threadIdx.x;
    const int wid  = tid >> 5;
    const int lane = tid & 31;
    const int warp_m = wid & 1;      // 0..1 -> 64-row slice of M
    const int warp_n = wid >> 1;     // 0..3 -> 32-col slice of N

    const int m0 = blockIdx.y * 128;   // channel tile
    const int n0 = blockIdx.x * 128;   // row tile

    const uint32_t sbase = smem_u32(smem);

    // per-thread copy mapping: 4 chunks of 16B for A, 4 for B per stage
    const int crow = tid >> 3;               // ...combined with i*32
    const int cc   = tid & 7;                // 16B chunk within 128B row

    float acc[4][4][4];
    #pragma unroll
    for (int i = 0; i < 4; i++)
        #pragma unroll
        for (int jq = 0; jq < 4; jq++)
            #pragma unroll
            for (int e = 0; e < 4; e++) acc[i][jq][e] = 0.0f;

    // stage issue: A rows m0.., B rows n0.., k-chunk base k0
    auto issue = [&](int st, int k0) {
        uint32_t aDst = sbase + st * STAGE_BYTES;
        uint32_t bDst = aDst + A_BYTES;
        #pragma unroll
        for (int i = 0; i < 4; i++) {
            int row = crow + i * 32;          // 0..127
            uint32_t doff = row * 128 + ((cc ^ (row & 7)) * 16);
            cp_async16(aDst + doff, g_w2 + (size_t)(m0 + row) * K2 + k0 + cc * 8);
            cp_async16(bDst + doff, g_c2 + (size_t)(n0 + row) * K2 + k0 + cc * 8);
        }
    };

    issue(0, 0);  CP_COMMIT();
    issue(1, BK); CP_COMMIT();

    for (int kt = 0; kt < NKITER; kt++) {
        CP_WAIT(1);
        __syncthreads();

        if (kt + 2 < NKITER) issue((kt + 2) % STAGES, (kt + 2) * BK);
        CP_COMMIT();

        const uint32_t aBase = sbase + (kt % STAGES) * STAGE_BYTES;
        const uint32_t bBase = aBase + A_BYTES;

        #pragma unroll
        for (int ks = 0; ks < 4; ks++) {       // k16 steps within BK=64
            uint32_t afr[4][4];
            #pragma unroll
            for (int mt = 0; mt < 4; mt++) {
                int row = warp_m * 64 + mt * 16 + (lane & 15);
                int ch  = (2 * ks + (lane >> 4)) ^ (row & 7);
                ldsm4(afr[mt], aBase + row * 128 + ch * 16);
            }
            uint32_t bfr[2][4];
            #pragma unroll
            for (int ntp = 0; ntp < 2; ntp++) {
                int row = warp_n * 32 + ntp * 16 + ((lane >> 4) << 3) + (lane & 7);
                int ch  = (2 * ks + ((lane >> 3) & 1)) ^ (row & 7);
                ldsm4(bfr[ntp], bBase + row * 128 + ch * 16);
            }
            #pragma unroll
            for (int mt = 0; mt < 4; mt++)
                #pragma unroll
                for (int nt = 0; nt < 4; nt++)
                    mma16816(acc[mt][nt], afr[mt], &bfr[nt >> 1][(nt & 1) * 2]);
        }
        __syncthreads();
    }

    // Epilogue: out[b, ch, pos];  n-tile (128 rows) stays within one batch.
    const int b    = n0 >> 10;
    const int pos0 = (n0 & 1023) + warp_n * 32 + (lane & 3) * 2;
    const int chb  = m0 + warp_m * 64 + (lane >> 2);
    #pragma unroll
    for (int mt = 0; mt < 4; mt++) {
        #pragma unroll
        for (int nt = 0; nt < 4; nt++) {
            float* o0 = out + ((size_t)b * NCH + chb + mt * 16) * 1024 + pos0 + nt * 8;
            *(float2*)o0            = make_float2(acc[mt][nt][0], acc[mt][nt][1]);
            *(float2*)(o0 + 8 * 1024) = make_float2(acc[mt][nt][2], acc[mt][nt][3]);
        }
    }
}

// ---------------------------------------------------------------------------
extern "C" void kernel_launch(void* const* d_in, const int* in_sizes, int n_in,
                              void* d_out, int out_size) {
    const float* x = (const float*)d_in[0];   // [8, 256, 32, 32]
    const float* w = (const float*)d_in[1];   // [8, 36, 64]
    float* out = (float*)d_out;               // [8, 512, 32, 32]

    cudaFuncSetAttribute(gemm_mma, cudaFuncAttributeMaxDynamicSharedMemorySize, SMEM_TOTAL);

    wexpand_split<<<(NCH * KDIM + 255) / 256, 256>>>(w);
    im2col_split<<<dim3(KDIM / 2 / 128, MPOS), 128>>>(x);
    gemm_mma<<<dim3(MPOS / 128, NCH / 128), 256, SMEM_TOTAL>>>(out);
}

// round 7
// speedup vs baseline: 5.8520x; 2.0119x over previous
#include <cuda_runtime.h>
#include <cuda_fp16.h>
#include <cstdint>

#define KDIM  2304
#define NCH   512
#define MPOS  8192
#define IN_CH 256

// Scratch globals (no runtime allocation allowed)
__device__ __half g_wf[(size_t)NCH  * KDIM];   // [ch][k]
__device__ __half g_cf[(size_t)MPOS * KDIM];   // [n][k]

// ---------------- helpers ----------------
static __device__ __forceinline__ uint32_t smem_u32(const void* p) {
    uint32_t a;
    asm("{ .reg .u64 t; cvta.to.shared.u64 t, %1; cvt.u32.u64 %0, t; }" : "=r"(a) : "l"(p));
    return a;
}
static __device__ __forceinline__ void cp_async16(uint32_t dst, const void* src) {
    asm volatile("cp.async.cg.shared.global [%0], [%1], 16;" :: "r"(dst), "l"(src));
}
#define CP_COMMIT() asm volatile("cp.async.commit_group;" ::: "memory")
#define CP_WAIT(N)  asm volatile("cp.async.wait_group %0;" :: "n"(N) : "memory")

static __device__ __forceinline__ void ldsm4(uint32_t* r, uint32_t a) {
    asm volatile("ldmatrix.sync.aligned.m8n8.x4.shared.b16 {%0,%1,%2,%3}, [%4];"
        : "=r"(r[0]), "=r"(r[1]), "=r"(r[2]), "=r"(r[3]) : "r"(a));
}
static __device__ __forceinline__ void mma16816(float* d, const uint32_t* a, const uint32_t* b) {
    asm volatile(
        "mma.sync.aligned.m16n8k16.row.col.f32.f16.f16.f32 "
        "{%0,%1,%2,%3}, {%4,%5,%6,%7}, {%8,%9}, {%0,%1,%2,%3};"
        : "+f"(d[0]), "+f"(d[1]), "+f"(d[2]), "+f"(d[3])
        : "r"(a[0]), "r"(a[1]), "r"(a[2]), "r"(a[3]), "r"(b[0]), "r"(b[1]));
}

// ---------------------------------------------------------------------------
// Kernel 1: circulant weight expansion -> fp16, K-major [ch][k]
// Wexp[ch = p*64+t][k = q*64+s] = w[p, q, (t-s)&63]
// ---------------------------------------------------------------------------
__global__ void wexpand_f16(const float* __restrict__ w) {
    int idx = blockIdx.x * blockDim.x + threadIdx.x;    // over 512*2304
    if (idx >= NCH * KDIM) return;
    int ch = idx / KDIM;
    int k  = idx - ch * KDIM;
    int p = ch >> 6, t = ch & 63;
    int q = k >> 6,  s = k & 63;
    g_wf[idx] = __float2half(w[(p * 36 + q) * 64 + ((t - s) & 63)]);
}

// ---------------------------------------------------------------------------
// Kernel 2: scrambled-reshape gather -> fp16, K-major [n][k]
// row n = b*1024+m reads xu_flat[n*2304+j]:
//   rem = m*2304+j; f = rem>>10; l = rem&1023
//   f = c*9+di*3+dj, l = i*32+jj, value = x[b,c,i+di-1,jj+dj-1] (zero-pad)
// ---------------------------------------------------------------------------
__global__ void im2col_f16(const float* __restrict__ x) {
    int j = (blockIdx.x * blockDim.x + threadIdx.x) * 2;   // even, 0..2302
    int n = blockIdx.y;
    int b = n >> 10;
    int m = n & 1023;
    float v[2];
    #pragma unroll
    for (int u = 0; u < 2; u++) {
        int rem = m * KDIM + j + u;
        int f = rem >> 10;
        int l = rem & 1023;
        int c  = f / 9;
        int r  = f - c * 9;
        int di = r / 3;
        int dj = r - di * 3;
        int i  = l >> 5;
        int jj = l & 31;
        int ii = i + di - 1;
        int jc = jj + dj - 1;
        float t = 0.0f;
        if ((unsigned)ii < 32u && (unsigned)jc < 32u)
            t = x[((b * IN_CH + c) * 32 + ii) * 32 + jc];
        v[u] = t;
    }
    *(__half2*)(g_cf + (size_t)n * KDIM + j) =
        __halves2half2(__float2half(v[0]), __float2half(v[1]));
}

// ---------------------------------------------------------------------------
// Kernel 3: fp16 mma.sync GEMM.  C[ch][n] = sum_k W[ch][k] * Col[n][k]
// BM=128, BN=128, BK=64, 3-stage cp.async pipeline, 8 warps (64x32 each).
// Smem rows = 128B (64 fp16), 3-bit xor swizzle -> conflict-free ldmatrix.
// ---------------------------------------------------------------------------
#define BK        64
#define NKITER    (KDIM / BK)        // 36
#define A_BYTES   (128 * 128)        // 16 KB
#define STAGE_BYTES (2 * A_BYTES)    // A + B = 32 KB
#define STAGES    3
#define SMEM_TOTAL (STAGES * STAGE_BYTES)   // 96 KB

__global__ __launch_bounds__(256, 2) void gemm_mma(float* __restrict__ out) {
    extern __shared__ char smem[];
    const int tid  = threadIdx.x;
    const int wid  = tid >> 5;
    const int lane = tid & 31;
    const int warp_m = wid & 1;      // 0..1 -> 64-row slice of M
    const int warp_n = wid >> 1;     // 0..3 -> 32-col slice of N

    const int m0 = blockIdx.y * 128;   // channel tile
    const int n0 = blockIdx.x * 128;   // row tile

    const uint32_t sbase = smem_u32(smem);

    const int crow = tid >> 3;               // 0..31 (plus i*32)
    const int cc   = tid & 7;                // 16B chunk within 128B row

    float acc[4][4][4];
    #pragma unroll
    for (int i = 0; i < 4; i++)
        #pragma unroll
        for (int jq = 0; jq < 4; jq++)
            #pragma unroll
            for (int e = 0; e < 4; e++) acc[i][jq][e] = 0.0f;

    auto issue = [&](int st, int k0) {
        uint32_t aDst = sbase + st * STAGE_BYTES;
        uint32_t bDst = aDst + A_BYTES;
        #pragma unroll
        for (int i = 0; i < 4; i++) {
            int row = crow + i * 32;          // 0..127
            uint32_t doff = row * 128 + ((cc ^ (row & 7)) * 16);
            cp_async16(aDst + doff, g_wf + (size_t)(m0 + row) * KDIM + k0 + cc * 8);
            cp_async16(bDst + doff, g_cf + (size_t)(n0 + row) * KDIM + k0 + cc * 8);
        }
    };

    issue(0, 0);  CP_COMMIT();
    issue(1, BK); CP_COMMIT();

    for (int kt = 0; kt < NKITER; kt++) {
        CP_WAIT(1);
        __syncthreads();

        if (kt + 2 < NKITER) issue((kt + 2) % STAGES, (kt + 2) * BK);
        CP_COMMIT();

        const uint32_t aBase = sbase + (kt % STAGES) * STAGE_BYTES;
        const uint32_t bBase = aBase + A_BYTES;

        #pragma unroll
        for (int ks = 0; ks < 4; ks++) {       // k16 steps within BK=64
            uint32_t afr[4][4];
            #pragma unroll
            for (int mt = 0; mt < 4; mt++) {
                int row = warp_m * 64 + mt * 16 + (lane & 15);
                int ch  = (2 * ks + (lane >> 4)) ^ (row & 7);
                ldsm4(afr[mt], aBase + row * 128 + ch * 16);
            }
            uint32_t bfr[2][4];
            #pragma unroll
            for (int ntp = 0; ntp < 2; ntp++) {
                int row = warp_n * 32 + ntp * 16 + ((lane >> 4) << 3) + (lane & 7);
                int ch  = (2 * ks + ((lane >> 3) & 1)) ^ (row & 7);
                ldsm4(bfr[ntp], bBase + row * 128 + ch * 16);
            }
            #pragma unroll
            for (int mt = 0; mt < 4; mt++)
                #pragma unroll
                for (int nt = 0; nt < 4; nt++)
                    mma16816(acc[mt][nt], afr[mt], &bfr[nt >> 1][(nt & 1) * 2]);
        }
        __syncthreads();
    }

    // Epilogue: out[b, ch, pos];  n-tile (128 rows) stays within one batch.
    const int b    = n0 >> 10;
    const int pos0 = (n0 & 1023) + warp_n * 32 + (lane & 3) * 2;
    const int chb  = m0 + warp_m * 64 + (lane >> 2);
    #pragma unroll
    for (int mt = 0; mt < 4; mt++) {
        #pragma unroll
        for (int nt = 0; nt < 4; nt++) {
            float* o0 = out + ((size_t)b * NCH + chb + mt * 16) * 1024 + pos0 + nt * 8;
            *(float2*)o0              = make_float2(acc[mt][nt][0], acc[mt][nt][1]);
            *(float2*)(o0 + 8 * 1024) = make_float2(acc[mt][nt][2], acc[mt][nt][3]);
        }
    }
}

// ---------------------------------------------------------------------------
extern "C" void kernel_launch(void* const* d_in, const int* in_sizes, int n_in,
                              void* d_out, int out_size) {
    const float* x = (const float*)d_in[0];   // [8, 256, 32, 32]
    const float* w = (const float*)d_in[1];   // [8, 36, 64]
    float* out = (float*)d_out;               // [8, 512, 32, 32]

    cudaFuncSetAttribute(gemm_mma, cudaFuncAttributeMaxDynamicSharedMemorySize, SMEM_TOTAL);

    wexpand_f16<<<(NCH * KDIM + 255) / 256, 256>>>(w);
    im2col_f16<<<dim3(KDIM / 2 / 128, MPOS), 128>>>(x);
    gemm_mma<<<dim3(MPOS / 128, NCH / 128), 256, SMEM_TOTAL>>>(out);
}

// round 8
// speedup vs baseline: 7.4428x; 1.2718x over previous
#include <cuda_runtime.h>
#include <cuda_fp16.h>
#include <cstdint>

#define KDIM  2304
#define NCH   512
#define MPOS  8192
#define IN_CH 256

// Scratch globals (no runtime allocation allowed)
__device__ __half g_wf[(size_t)NCH  * KDIM];   // [ch][k]
__device__ __half g_cf[(size_t)MPOS * KDIM];   // [n][k] == natural unfold (b,f,l)

union Pack8 { __half h[8]; uint4 u; };

// ---------------- helpers ----------------
static __device__ __forceinline__ uint32_t smem_u32(const void* p) {
    uint32_t a;
    asm("{ .reg .u64 t; cvta.to.shared.u64 t, %1; cvt.u32.u64 %0, t; }" : "=r"(a) : "l"(p));
    return a;
}
static __device__ __forceinline__ void cp_async16(uint32_t dst, const void* src) {
    asm volatile("cp.async.cg.shared.global [%0], [%1], 16;" :: "r"(dst), "l"(src));
}
#define CP_COMMIT() asm volatile("cp.async.commit_group;" ::: "memory")
#define CP_WAIT(N)  asm volatile("cp.async.wait_group %0;" :: "n"(N) : "memory")

static __device__ __forceinline__ void ldsm4(uint32_t* r, uint32_t a) {
    asm volatile("ldmatrix.sync.aligned.m8n8.x4.shared.b16 {%0,%1,%2,%3}, [%4];"
        : "=r"(r[0]), "=r"(r[1]), "=r"(r[2]), "=r"(r[3]) : "r"(a));
}
static __device__ __forceinline__ void mma16816(float* d, const uint32_t* a, const uint32_t* b) {
    asm volatile(
        "mma.sync.aligned.m16n8k16.row.col.f32.f16.f16.f32 "
        "{%0,%1,%2,%3}, {%4,%5,%6,%7}, {%8,%9}, {%0,%1,%2,%3};"
        : "+f"(d[0]), "+f"(d[1]), "+f"(d[2]), "+f"(d[3])
        : "r"(a[0]), "r"(a[1]), "r"(a[2]), "r"(a[3]), "r"(b[0]), "r"(b[1]));
}

// ---------------------------------------------------------------------------
// Fused prep kernel.
//  Blocks [0, 288):    wexpand. blk = p*36+q. Stage w-row in smem;
//                      g_wf[p*64+t][q*64+s] = wrow[(t-s)&63], 16B stores.
//  Blocks [288, +8*2304): natural-order unfold. blk-288 = b*2304 + f,
//                      f = c*9+di*3+dj; thread t covers l = t*8..t*8+7:
//                      g_cf_linear[b*2359296 + f*1024 + l] =
//                          fp16(x[b,c, (l>>5)+di-1, (l&31)+dj-1])  (zero pad).
//  The [n][k] GEMM operand is this same linear buffer (index identity:
//  (b*1024+m)*2304+k  ==  b*2359296 + f*1024 + l  with  m*2304+k = f*1024+l).
// ---------------------------------------------------------------------------
#define WBLOCKS 288
__global__ void prep_kernel(const float* __restrict__ x, const float* __restrict__ w) {
    const int blk = blockIdx.x;
    const int tid = threadIdx.x;

    if (blk < WBLOCKS) {
        __shared__ float wrow[64];
        const int p = blk / 36, q = blk - p * 36;
        if (tid < 64) wrow[tid] = w[blk * 64 + tid];
        __syncthreads();
        const int t  = tid >> 1;             // 0..63
        const int s0 = (tid & 1) * 32;       // 0 or 32
        const size_t base = (size_t)(p * 64 + t) * KDIM + q * 64 + s0;
        #pragma unroll
        for (int u = 0; u < 4; u++) {
            Pack8 pk;
            #pragma unroll
            for (int e = 0; e < 8; e++)
                pk.h[e] = __float2half(wrow[(t - (s0 + u * 8 + e)) & 63]);
            *(uint4*)(g_wf + base + u * 8) = pk.u;
        }
        return;
    }

    const int idx = blk - WBLOCKS;           // 0 .. 8*2304-1
    const int b = idx / KDIM;
    const int f = idx - b * KDIM;
    const int c = f / 9;
    const int r = f - c * 9;
    const int di = r / 3;
    const int dj = r - di * 3;

    const int l0  = tid * 8;                 // 128 threads x 8 elements
    const int i   = l0 >> 5;
    const int jj0 = l0 & 31;
    const int ii  = i + di - 1;
    const bool rowok = (unsigned)ii < 32u;
    const float* xr = x + ((size_t)(b * IN_CH + c) * 32 + ii) * 32;

    Pack8 pk;
    #pragma unroll
    for (int e = 0; e < 8; e++) {
        int jc = jj0 + e + dj - 1;
        float v = (rowok && (unsigned)jc < 32u) ? xr[jc] : 0.0f;
        pk.h[e] = __float2half(v);
    }
    *(uint4*)(g_cf + ((size_t)b * KDIM + f) * 1024 + l0) = pk.u;
}

// ---------------------------------------------------------------------------
// fp16 mma.sync GEMM.  C[ch][n] = sum_k W[ch][k] * Col[n][k]
// BM=128, BN=128, BK=64, 3-stage cp.async pipeline, 8 warps (64x32 each).
// Smem rows = 128B (64 fp16), 3-bit xor swizzle -> conflict-free ldmatrix.
// (unchanged from the 99.3us passing kernel)
// ---------------------------------------------------------------------------
#define BK        64
#define NKITER    (KDIM / BK)        // 36
#define A_BYTES   (128 * 128)        // 16 KB
#define STAGE_BYTES (2 * A_BYTES)    // A + B = 32 KB
#define STAGES    3
#define SMEM_TOTAL (STAGES * STAGE_BYTES)   // 96 KB

__global__ __launch_bounds__(256, 2) void gemm_mma(float* __restrict__ out) {
    extern __shared__ char smem[];
    const int tid  = threadIdx.x;
    const int wid  = tid >> 5;
    const int lane = tid & 31;
    const int warp_m = wid & 1;      // 0..1 -> 64-row slice of M
    const int warp_n = wid >> 1;     // 0..3 -> 32-col slice of N

    const int m0 = blockIdx.y * 128;   // channel tile
    const int n0 = blockIdx.x * 128;   // row tile

    const uint32_t sbase = smem_u32(smem);

    const int crow = tid >> 3;               // 0..31 (plus i*32)
    const int cc   = tid & 7;                // 16B chunk within 128B row

    float acc[4][4][4];
    #pragma unroll
    for (int i = 0; i < 4; i++)
        #pragma unroll
        for (int jq = 0; jq < 4; jq++)
            #pragma unroll
            for (int e = 0; e < 4; e++) acc[i][jq][e] = 0.0f;

    auto issue = [&](int st, int k0) {
        uint32_t aDst = sbase + st * STAGE_BYTES;
        uint32_t bDst = aDst + A_BYTES;
        #pragma unroll
        for (int i = 0; i < 4; i++) {
            int row = crow + i * 32;          // 0..127
            uint32_t doff = row * 128 + ((cc ^ (row & 7)) * 16);
            cp_async16(aDst + doff, g_wf + (size_t)(m0 + row) * KDIM + k0 + cc * 8);
            cp_async16(bDst + doff, g_cf + (size_t)(n0 + row) * KDIM + k0 + cc * 8);
        }
    };

    issue(0, 0);  CP_COMMIT();
    issue(1, BK); CP_COMMIT();

    for (int kt = 0; kt < NKITER; kt++) {
        CP_WAIT(1);
        __syncthreads();

        if (kt + 2 < NKITER) issue((kt + 2) % STAGES, (kt + 2) * BK);
        CP_COMMIT();

        const uint32_t aBase = sbase + (kt % STAGES) * STAGE_BYTES;
        const uint32_t bBase = aBase + A_BYTES;

        #pragma unroll
        for (int ks = 0; ks < 4; ks++) {       // k16 steps within BK=64
            uint32_t afr[4][4];
            #pragma unroll
            for (int mt = 0; mt < 4; mt++) {
                int row = warp_m * 64 + mt * 16 + (lane & 15);
                int ch  = (2 * ks + (lane >> 4)) ^ (row & 7);
                ldsm4(afr[mt], aBase + row * 128 + ch * 16);
            }
            uint32_t bfr[2][4];
            #pragma unroll
            for (int ntp = 0; ntp < 2; ntp++) {
                int row = warp_n * 32 + ntp * 16 + ((lane >> 4) << 3) + (lane & 7);
                int ch  = (2 * ks + ((lane >> 3) & 1)) ^ (row & 7);
                ldsm4(bfr[ntp], bBase + row * 128 + ch * 16);
            }
            #pragma unroll
            for (int mt = 0; mt < 4; mt++)
                #pragma unroll
                for (int nt = 0; nt < 4; nt++)
                    mma16816(acc[mt][nt], afr[mt], &bfr[nt >> 1][(nt & 1) * 2]);
        }
        __syncthreads();
    }

    // Epilogue: out[b, ch, pos];  n-tile (128 rows) stays within one batch.
    const int b    = n0 >> 10;
    const int pos0 = (n0 & 1023) + warp_n * 32 + (lane & 3) * 2;
    const int chb  = m0 + warp_m * 64 + (lane >> 2);
    #pragma unroll
    for (int mt = 0; mt < 4; mt++) {
        #pragma unroll
        for (int nt = 0; nt < 4; nt++) {
            float* o0 = out + ((size_t)b * NCH + chb + mt * 16) * 1024 + pos0 + nt * 8;
            *(float2*)o0              = make_float2(acc[mt][nt][0], acc[mt][nt][1]);
            *(float2*)(o0 + 8 * 1024) = make_float2(acc[mt][nt][2], acc[mt][nt][3]);
        }
    }
}

// ---------------------------------------------------------------------------
extern "C" void kernel_launch(void* const* d_in, const int* in_sizes, int n_in,
                              void* d_out, int out_size) {
    const float* x = (const float*)d_in[0];   // [8, 256, 32, 32]
    const float* w = (const float*)d_in[1];   // [8, 36, 64]
    float* out = (float*)d_out;               // [8, 512, 32, 32]

    cudaFuncSetAttribute(gemm_mma, cudaFuncAttributeMaxDynamicSharedMemorySize, SMEM_TOTAL);

    prep_kernel<<<WBLOCKS + 8 * KDIM, 128>>>(x, w);
    gemm_mma<<<dim3(MPOS / 128, NCH / 128), 256, SMEM_TOTAL>>>(out);
}